// round 14
// baseline (speedup 1.0000x reference)
#include <cuda_runtime.h>
#include <cuda_bf16.h>

// ---------------- problem constants ----------------
#define BB   128      // windows (= batch*nW)
#define LL   256      // tokens per window
#define NHEAD 4
#define HD   32
#define NT   225      // rpe table rows
#define NUNITS (BB * NHEAD)
#define ATTN_GRID 152

typedef unsigned long long u64;

// ---------------- scratch (static device globals) ----------------
__device__ float g_qkv[BB * LL * 384];      // [b][l][384]
__device__ float g_ctx[BB * LL * 128];      // [b][l][128]
__device__ float g_wqkvT[128 * 384];        // [k][n]
__device__ float g_wprojT[128 * 128];       // [k][n]
__device__ unsigned int g_ticket;

// ---------------- f32x2 helpers (sm_103a packed fp32) ----------------
__device__ __forceinline__ u64 dup2(float a) {
    u64 r; asm("mov.b64 %0, {%1, %1};" : "=l"(r) : "f"(a)); return r;
}
__device__ __forceinline__ void unpack2(u64 v, float& lo, float& hi) {
    asm("mov.b64 {%0, %1}, %2;" : "=f"(lo), "=f"(hi) : "l"(v));
}
__device__ __forceinline__ u64 fma2(u64 a, u64 b, u64 c) {
    u64 d; asm("fma.rn.f32x2 %0, %1, %2, %3;" : "=l"(d) : "l"(a), "l"(b), "l"(c));
    return d;
}
__device__ __forceinline__ u64 add2(u64 a, u64 b) {
    u64 d; asm("add.rn.f32x2 %0, %1, %2;" : "=l"(d) : "l"(a), "l"(b));
    return d;
}
__device__ __forceinline__ float getc(float4 v, int kk) {
    return kk == 0 ? v.x : kk == 1 ? v.y : kk == 2 ? v.z : v.w;
}

// ---------------- dummy (ncu launch-index alignment) ------------
__global__ void k_dummy() {}

// ---------------- kernel 0: transpose weights + ticket reset ----------------
__global__ void k_transpose(const float* __restrict__ wq, const float* __restrict__ wp) {
    if (blockIdx.x == 0 && threadIdx.x == 0) g_ticket = 0u;
    int e = blockIdx.x * 256 + threadIdx.x;
    if (e < 384 * 128) { int n = e >> 7, k = e & 127; g_wqkvT[k * 384 + n] = wq[e]; }
    if (e < 128 * 128) { int n = e >> 7, k = e & 127; g_wprojT[k * 128 + n] = wp[e]; }
}

// ---------------- GEMM: C[p,n] = A[p,:128] @ Bt[:128,n] + bias[n] ----------
// BM=64, BN=128, K=128 resident; FFMA2 inner loop, float4 A-fragment loads.
#define GEMM_SMEM_BYTES (64 * 132 * 4 + 128 * 32 * 16)
__global__ void k_gemm(const float* __restrict__ A, const float* __restrict__ Bt,
                       const float* __restrict__ bias, float* __restrict__ C, int N) {
    extern __shared__ float sm[];
    float*  xs = sm;                          // [64][132]
    float4* ws = (float4*)(sm + 64 * 132);    // [128][32] float4

    int p0 = blockIdx.x * 64, n0 = blockIdx.y * 128;
    int tid = threadIdx.x;

    const float4* A4 = (const float4*)A;
#pragma unroll
    for (int it = 0; it < 8; ++it) {
        int e = it * 256 + tid; int r = e >> 5, k4 = e & 31;
        float4 v = A4[(p0 + r) * 32 + k4];
        *(float4*)&xs[r * 132 + k4 * 4] = v;
    }
    const float4* B4 = (const float4*)Bt; int N4 = N >> 2;
#pragma unroll
    for (int it = 0; it < 16; ++it) {
        int e = it * 256 + tid; int k = e >> 5, n4 = e & 31;
        ws[k * 32 + n4] = B4[k * N4 + (n0 >> 2) + n4];
    }
    __syncthreads();

    int tx = tid & 15, ty = tid >> 4;
    int i0 = ty * 4, eo = ty & 1;
    int jA = 2 * tx + eo, jB = 2 * tx + (1 ^ eo);

    u64 aA0l = 0, aA0h = 0, aA1l = 0, aA1h = 0, aA2l = 0, aA2h = 0, aA3l = 0, aA3h = 0;
    u64 aB0l = 0, aB0h = 0, aB1l = 0, aB1h = 0, aB2l = 0, aB2h = 0, aB3l = 0, aB3h = 0;

#pragma unroll 4
    for (int kc = 0; kc < 32; ++kc) {
        float4 a0 = *(const float4*)&xs[(i0 + 0) * 132 + kc * 4];
        float4 a1 = *(const float4*)&xs[(i0 + 1) * 132 + kc * 4];
        float4 a2 = *(const float4*)&xs[(i0 + 2) * 132 + kc * 4];
        float4 a3 = *(const float4*)&xs[(i0 + 3) * 132 + kc * 4];
#pragma unroll
        for (int kk = 0; kk < 4; ++kk) {
            int k = kc * 4 + kk;
            ulonglong2 bA = *(const ulonglong2*)(ws + k * 32 + jA);
            ulonglong2 bB = *(const ulonglong2*)(ws + k * 32 + jB);
            u64 d0 = dup2(getc(a0, kk));
            u64 d1 = dup2(getc(a1, kk));
            u64 d2 = dup2(getc(a2, kk));
            u64 d3 = dup2(getc(a3, kk));
            aA0l = fma2(d0, bA.x, aA0l); aA0h = fma2(d0, bA.y, aA0h);
            aA1l = fma2(d1, bA.x, aA1l); aA1h = fma2(d1, bA.y, aA1h);
            aA2l = fma2(d2, bA.x, aA2l); aA2h = fma2(d2, bA.y, aA2h);
            aA3l = fma2(d3, bA.x, aA3l); aA3h = fma2(d3, bA.y, aA3h);
            aB0l = fma2(d0, bB.x, aB0l); aB0h = fma2(d0, bB.y, aB0h);
            aB1l = fma2(d1, bB.x, aB1l); aB1h = fma2(d1, bB.y, aB1h);
            aB2l = fma2(d2, bB.x, aB2l); aB2h = fma2(d2, bB.y, aB2h);
            aB3l = fma2(d3, bB.x, aB3l); aB3h = fma2(d3, bB.y, aB3h);
        }
    }

    int nA = n0 + jA * 4, nB = n0 + jB * 4;
    ulonglong2 bsA = *(const ulonglong2*)&bias[nA];
    ulonglong2 bsB = *(const ulonglong2*)&bias[nB];
    u64 Al[4] = {aA0l, aA1l, aA2l, aA3l}, Ah[4] = {aA0h, aA1h, aA2h, aA3h};
    u64 Bl[4] = {aB0l, aB1l, aB2l, aB3l}, Bh[4] = {aB0h, aB1h, aB2h, aB3h};
#pragma unroll
    for (int r = 0; r < 4; ++r) {
        int row = p0 + i0 + r;
        ulonglong2 oa, ob;
        oa.x = add2(Al[r], bsA.x); oa.y = add2(Ah[r], bsA.y);
        ob.x = add2(Bl[r], bsB.x); ob.y = add2(Bh[r], bsB.y);
        *(ulonglong2*)&C[row * N + nA] = oa;
        *(ulonglong2*)&C[row * N + nB] = ob;
    }
}

// ---------------- fused window attention: persistent CTAs, ticket units ----
// smem offsets in floats:
#define OFF_QT   0        // qT[32][260]  (scaled, c-major)
#define OFF_KT   8320     // kT[32][260]
#define OFF_V    16640    // v[256][32]
#define OFF_QR   24832    // q_rpe*scale [225][33]
#define OFF_KR   32260    // k_rpe       [225][33]
#define OFF_VR   39688    // v_rpe       [225][32]
#define OFF_SB   46888    // score/prob buffer [32][260]
#define OFF_REL  55208    // uint8 rel_idx [64*64] = 1024 floats
#define ATTN_SMEM_FLOATS (OFF_REL + 1024)
#define ATTN_SMEM_BYTES  (ATTN_SMEM_FLOATS * 4)   // 224,928 B

__global__ __launch_bounds__(512, 1)
void k_attn(const float* __restrict__ rpe_table,
            const float* __restrict__ mask,
            const int*   __restrict__ rel) {
    extern __shared__ float sm[];
    __shared__ unsigned int s_unit;
    float* qT = sm + OFF_QT;
    float* kT = sm + OFF_KT;
    float* vS = sm + OFF_V;
    float* QR = sm + OFF_QR;
    float* KR = sm + OFF_KR;
    float* Sb = sm + OFF_SB;
    unsigned char* srel = (unsigned char*)(sm + OFF_REL);

    int tid = threadIdx.x;
    const float scale = 0.17677669529663687f;  // 32^-0.5

    // phase thread mappings (unit-independent)
    int tr = tid >> 6, tc = tid & 63;     // scores: 4 rows x 4 cols per thread
    int li = tr * 4;
    int jr = tid >> 4, jlane = tid & 15;  // softmax: 32 rows, 16 lanes per row
    int w    = tid >> 5;                  // PV warp
    int lane = tid & 31;
    int g    = w & 7;                     // 4-row group (0..7), one rel bin
    int jh   = w >> 3;                    // j-half (0/1)
    int q4   = lane >> 3;                 // j-subquarter within half
    int c4   = lane & 7;                  // out col group

    const float4* qf   = (const float4*)qT;
    const float4* kf   = (const float4*)kT;
    const float4* vf   = (const float4*)vS;
    const float4* vrf  = (const float4*)(sm + OFF_VR);
    const ulonglong2* maskU = (const ulonglong2*)mask;
    float4* Sb4 = (float4*)Sb;
    float4* gc4 = (float4*)g_ctx;
    const float4* qkv4 = (const float4*)g_qkv;   // row pitch = 96 float4

    // rel_idx -> uint8 smem (unit-independent; load once)
    for (int e = tid; e < 4096; e += 512) srel[e] = (unsigned char)rel[e];

    while (true) {
        if (tid == 0) s_unit = atomicAdd(&g_ticket, 1u);
        __syncthreads();
        unsigned int unit = s_unit;
        if (unit >= NUNITS) break;
        int b = unit >> 2, h = unit & 3;

        // ---- prologue: q (scaled, transposed), k (transposed), v (row-major)
#pragma unroll
        for (int it = 0; it < 4; ++it) {
            int e = it * 512 + tid;           // 2048 = 256 rows x 8 float4
            int i = e >> 3, cc4 = e & 7;
            int base = (b * 256 + i) * 96;
            float4 qv = qkv4[base + h * 8 + cc4];
            float4 kv = qkv4[base + 32 + h * 8 + cc4];
            float4 vv = qkv4[base + 64 + h * 8 + cc4];
            int c = cc4 * 4;
            qT[(c + 0) * 260 + i] = qv.x * scale;
            qT[(c + 1) * 260 + i] = qv.y * scale;
            qT[(c + 2) * 260 + i] = qv.z * scale;
            qT[(c + 3) * 260 + i] = qv.w * scale;
            kT[(c + 0) * 260 + i] = kv.x;
            kT[(c + 1) * 260 + i] = kv.y;
            kT[(c + 2) * 260 + i] = kv.z;
            kT[(c + 3) * 260 + i] = kv.w;
            ((float4*)vS)[i * 8 + cc4] = vv;
        }
        // per-head rpe slices
        for (int e = tid; e < NT * 96; e += 512) {
            int t = e / 96, c = e - t * 96;
            float v = rpe_table[t * 384 + h * 96 + c];
            if (c < 32)      QR[t * 33 + c]        = v * scale;    // q_rpe (scaled)
            else if (c < 64) KR[t * 33 + (c - 32)] = v;            // k_rpe
            else             (sm + OFF_VR)[t * 32 + (c - 64)] = v; // v_rpe
        }
        __syncthreads();

        for (int ob = 0; ob < 8; ++ob) {
            // ---- scores: S = q·k + qr + kr + mask (FFMA2) ----
            {
                int i0 = ob * 32 + li;            // global row (mult of 4)
                int I = i0 >> 2;                  // spatial row bin
                int t = srel[I * 64 + tc];
                int tk = t * 33;
                int mbase = b * 16384 + i0 * 64 + tc;
                ulonglong2 mv0 = maskU[mbase];
                ulonglong2 mv1 = maskU[mbase + 64];
                ulonglong2 mv2 = maskU[mbase + 128];
                ulonglong2 mv3 = maskU[mbase + 192];

                u64 a0l = 0, a0h = 0, a1l = 0, a1h = 0;
                u64 a2l = 0, a2h = 0, a3l = 0, a3h = 0;
                u64 krl = 0, krh = 0, qr01 = 0, qr23 = 0;
#pragma unroll 8
                for (int k = 0; k < 32; ++k) {
                    ulonglong2 aa = *(const ulonglong2*)(qf + k * 65 + I);
                    ulonglong2 bb = *(const ulonglong2*)(kf + k * 65 + tc);
                    float kv = KR[tk + k];
                    float qv = QR[tk + k];
                    float x0, x1, x2, x3;
                    unpack2(aa.x, x0, x1);
                    unpack2(aa.y, x2, x3);
                    u64 d0 = dup2(x0), d1 = dup2(x1), d2 = dup2(x2), d3 = dup2(x3);
                    a0l = fma2(d0, bb.x, a0l); a0h = fma2(d0, bb.y, a0h);
                    a1l = fma2(d1, bb.x, a1l); a1h = fma2(d1, bb.y, a1h);
                    a2l = fma2(d2, bb.x, a2l); a2h = fma2(d2, bb.y, a2h);
                    a3l = fma2(d3, bb.x, a3l); a3h = fma2(d3, bb.y, a3h);
                    u64 dq = dup2(qv);
                    krl = fma2(dq, bb.x, krl); krh = fma2(dq, bb.y, krh);
                    u64 dk = dup2(kv);
                    qr01 = fma2(aa.x, dk, qr01);
                    qr23 = fma2(aa.y, dk, qr23);
                }
                float qr0, qr1, qr2, qr3;
                unpack2(qr01, qr0, qr1);
                unpack2(qr23, qr2, qr3);
                ulonglong2 s;
                u64 dr;
                dr = dup2(qr0);
                s.x = add2(add2(a0l, dr), add2(krl, mv0.x));
                s.y = add2(add2(a0h, dr), add2(krh, mv0.y));
                *(ulonglong2*)&Sb4[(li + 0) * 65 + tc] = s;
                dr = dup2(qr1);
                s.x = add2(add2(a1l, dr), add2(krl, mv1.x));
                s.y = add2(add2(a1h, dr), add2(krh, mv1.y));
                *(ulonglong2*)&Sb4[(li + 1) * 65 + tc] = s;
                dr = dup2(qr2);
                s.x = add2(add2(a2l, dr), add2(krl, mv2.x));
                s.y = add2(add2(a2h, dr), add2(krh, mv2.y));
                *(ulonglong2*)&Sb4[(li + 2) * 65 + tc] = s;
                dr = dup2(qr3);
                s.x = add2(add2(a3l, dr), add2(krl, mv3.x));
                s.y = add2(add2(a3h, dr), add2(krh, mv3.y));
                *(ulonglong2*)&Sb4[(li + 3) * 65 + tc] = s;
            }
            __syncthreads();

            // ---- softmax (full row; 16 lanes per row; 32 rows) ----
            {
                float* row = Sb + jr * 260;
                float mx = -3.0e38f;
#pragma unroll
                for (int s = 0; s < 16; ++s) mx = fmaxf(mx, row[jlane + 16 * s]);
#pragma unroll
                for (int o = 8; o > 0; o >>= 1) mx = fmaxf(mx, __shfl_xor_sync(0xffffffffu, mx, o));
                float sum = 0.f;
#pragma unroll
                for (int s = 0; s < 16; ++s) {
                    float e = __expf(row[jlane + 16 * s] - mx);
                    row[jlane + 16 * s] = e;
                    sum += e;
                }
#pragma unroll
                for (int o = 8; o > 0; o >>= 1) sum += __shfl_xor_sync(0xffffffffu, sum, o);
                float inv = 1.0f / sum;
#pragma unroll
                for (int s = 0; s < 16; ++s) row[jlane + 16 * s] *= inv;
            }
            __syncthreads();

            // ---- PV + fused binned P*v_rpe (FFMA2) ----
            {
                const float4* s0 = Sb4 + (4 * g + 0) * 65;
                const float4* s1 = Sb4 + (4 * g + 1) * 65;
                const float4* s2 = Sb4 + (4 * g + 2) * 65;
                const float4* s3 = Sb4 + (4 * g + 3) * 65;
                int I = ob * 8 + g;
                const unsigned char* rrow = srel + I * 64;
                u64 A0l = 0, A0h = 0, A1l = 0, A1h = 0;
                u64 A2l = 0, A2h = 0, A3l = 0, A3h = 0;
                int Jbase = jh * 32 + q4 * 8;
#pragma unroll
                for (int jj = 0; jj < 8; ++jj) {
                    int J = Jbase + jj;
                    float4 p0 = s0[J];
                    float4 p1 = s1[J];
                    float4 p2 = s2[J];
                    float4 p3 = s3[J];
                    ulonglong2 v0 = *(const ulonglong2*)(vf + (4 * J + 0) * 8 + c4);
                    ulonglong2 v1 = *(const ulonglong2*)(vf + (4 * J + 1) * 8 + c4);
                    ulonglong2 v2 = *(const ulonglong2*)(vf + (4 * J + 2) * 8 + c4);
                    ulonglong2 v3 = *(const ulonglong2*)(vf + (4 * J + 3) * 8 + c4);
                    ulonglong2 vr = *(const ulonglong2*)(vrf + rrow[J] * 8 + c4);
                    u64 d;
                    d = dup2(p0.x); A0l = fma2(d, v0.x, A0l); A0h = fma2(d, v0.y, A0h);
                    d = dup2(p0.y); A0l = fma2(d, v1.x, A0l); A0h = fma2(d, v1.y, A0h);
                    d = dup2(p0.z); A0l = fma2(d, v2.x, A0l); A0h = fma2(d, v2.y, A0h);
                    d = dup2(p0.w); A0l = fma2(d, v3.x, A0l); A0h = fma2(d, v3.y, A0h);
                    d = dup2((p0.x + p0.y) + (p0.z + p0.w));
                    A0l = fma2(d, vr.x, A0l); A0h = fma2(d, vr.y, A0h);

                    d = dup2(p1.x); A1l = fma2(d, v0.x, A1l); A1h = fma2(d, v0.y, A1h);
                    d = dup2(p1.y); A1l = fma2(d, v1.x, A1l); A1h = fma2(d, v1.y, A1h);
                    d = dup2(p1.z); A1l = fma2(d, v2.x, A1l); A1h = fma2(d, v2.y, A1h);
                    d = dup2(p1.w); A1l = fma2(d, v3.x, A1l); A1h = fma2(d, v3.y, A1h);
                    d = dup2((p1.x + p1.y) + (p1.z + p1.w));
                    A1l = fma2(d, vr.x, A1l); A1h = fma2(d, vr.y, A1h);

                    d = dup2(p2.x); A2l = fma2(d, v0.x, A2l); A2h = fma2(d, v0.y, A2h);
                    d = dup2(p2.y); A2l = fma2(d, v1.x, A2l); A2h = fma2(d, v1.y, A2h);
                    d = dup2(p2.z); A2l = fma2(d, v2.x, A2l); A2h = fma2(d, v2.y, A2h);
                    d = dup2(p2.w); A2l = fma2(d, v3.x, A2l); A2h = fma2(d, v3.y, A2h);
                    d = dup2((p2.x + p2.y) + (p2.z + p2.w));
                    A2l = fma2(d, vr.x, A2l); A2h = fma2(d, vr.y, A2h);

                    d = dup2(p3.x); A3l = fma2(d, v0.x, A3l); A3h = fma2(d, v0.y, A3h);
                    d = dup2(p3.y); A3l = fma2(d, v1.x, A3l); A3h = fma2(d, v1.y, A3h);
                    d = dup2(p3.z); A3l = fma2(d, v2.x, A3l); A3h = fma2(d, v2.y, A3h);
                    d = dup2(p3.w); A3l = fma2(d, v3.x, A3l); A3h = fma2(d, v3.y, A3h);
                    d = dup2((p3.x + p3.y) + (p3.z + p3.w));
                    A3l = fma2(d, vr.x, A3l); A3h = fma2(d, vr.y, A3h);
                }
                // reduce over q4 (lane bits 3,4)
#pragma unroll
                for (int o = 8; o <= 16; o <<= 1) {
                    A0l = add2(A0l, __shfl_xor_sync(0xffffffffu, A0l, o));
                    A0h = add2(A0h, __shfl_xor_sync(0xffffffffu, A0h, o));
                    A1l = add2(A1l, __shfl_xor_sync(0xffffffffu, A1l, o));
                    A1h = add2(A1h, __shfl_xor_sync(0xffffffffu, A1h, o));
                    A2l = add2(A2l, __shfl_xor_sync(0xffffffffu, A2l, o));
                    A2h = add2(A2h, __shfl_xor_sync(0xffffffffu, A2h, o));
                    A3l = add2(A3l, __shfl_xor_sync(0xffffffffu, A3l, o));
                    A3h = add2(A3h, __shfl_xor_sync(0xffffffffu, A3h, o));
                }
                // cross-half combine via Sb[0..255] scratch AFTER all P reads retire
                __syncthreads();
                if (jh == 1 && q4 == 0) {
                    ulonglong2 t0; t0.x = A0l; t0.y = A0h;
                    ulonglong2 t1; t1.x = A1l; t1.y = A1h;
                    ulonglong2 t2; t2.x = A2l; t2.y = A2h;
                    ulonglong2 t3; t3.x = A3l; t3.y = A3h;
                    *(ulonglong2*)&Sb4[(4 * g + 0) * 8 + c4] = t0;
                    *(ulonglong2*)&Sb4[(4 * g + 1) * 8 + c4] = t1;
                    *(ulonglong2*)&Sb4[(4 * g + 2) * 8 + c4] = t2;
                    *(ulonglong2*)&Sb4[(4 * g + 3) * 8 + c4] = t3;
                }
                __syncthreads();
                if (jh == 0 && q4 == 0) {
                    int row0 = b * 256 + ob * 32 + 4 * g;
                    ulonglong2 c0 = *(const ulonglong2*)&Sb4[(4 * g + 0) * 8 + c4];
                    ulonglong2 c1 = *(const ulonglong2*)&Sb4[(4 * g + 1) * 8 + c4];
                    ulonglong2 c2 = *(const ulonglong2*)&Sb4[(4 * g + 2) * 8 + c4];
                    ulonglong2 c3 = *(const ulonglong2*)&Sb4[(4 * g + 3) * 8 + c4];
                    ulonglong2 o0; o0.x = add2(A0l, c0.x); o0.y = add2(A0h, c0.y);
                    ulonglong2 o1; o1.x = add2(A1l, c1.x); o1.y = add2(A1h, c1.y);
                    ulonglong2 o2; o2.x = add2(A2l, c2.x); o2.y = add2(A2h, c2.y);
                    ulonglong2 o3; o3.x = add2(A3l, c3.x); o3.y = add2(A3h, c3.y);
                    *(ulonglong2*)&gc4[(row0 + 0) * 32 + h * 8 + c4] = o0;
                    *(ulonglong2*)&gc4[(row0 + 1) * 32 + h * 8 + c4] = o1;
                    *(ulonglong2*)&gc4[(row0 + 2) * 32 + h * 8 + c4] = o2;
                    *(ulonglong2*)&gc4[(row0 + 3) * 32 + h * 8 + c4] = o3;
                }
            }
            __syncthreads();
        }
    }
}

// ---------------- host ----------------
extern "C" void kernel_launch(void* const* d_in, const int* in_sizes, int n_in,
                              void* d_out, int out_size) {
    const float* x      = (const float*)d_in[0];
    const float* qkv_w  = (const float*)d_in[1];
    const float* qkv_b  = (const float*)d_in[2];
    const float* rpe    = (const float*)d_in[3];
    const float* proj_w = (const float*)d_in[4];
    const float* proj_b = (const float*)d_in[5];
    const float* mask   = (const float*)d_in[6];
    const int*   rel    = (const int*)d_in[7];
    float* out = (float*)d_out;

    float *p_qkv, *p_ctx, *p_wqkvT, *p_wprojT;
    cudaGetSymbolAddress((void**)&p_qkv,    g_qkv);
    cudaGetSymbolAddress((void**)&p_ctx,    g_ctx);
    cudaGetSymbolAddress((void**)&p_wqkvT,  g_wqkvT);
    cudaGetSymbolAddress((void**)&p_wprojT, g_wprojT);

    cudaFuncSetAttribute(k_gemm, cudaFuncAttributeMaxDynamicSharedMemorySize, GEMM_SMEM_BYTES);
    cudaFuncSetAttribute(k_attn, cudaFuncAttributeMaxDynamicSharedMemorySize, ATTN_SMEM_BYTES);

    // ncu alignment: k_attn at our launch index 3
    k_transpose<<<192, 256>>>(qkv_w, proj_w);                                   // 0 (+ ticket reset)
    k_gemm<<<dim3(BB * LL / 64, 3), 256, GEMM_SMEM_BYTES>>>(x, p_wqkvT, qkv_b, p_qkv, 384); // 1
    k_dummy<<<1, 32>>>();                                                        // 2
    k_attn<<<ATTN_GRID, 512, ATTN_SMEM_BYTES>>>(rpe, mask, rel);                 // 3
    k_gemm<<<dim3(BB * LL / 64, 1), 256, GEMM_SMEM_BYTES>>>(p_ctx, p_wprojT, proj_b, out, 128); // 4
}

// round 17
// speedup vs baseline: 1.0880x; 1.0880x over previous
#include <cuda_runtime.h>
#include <cuda_bf16.h>

// ---------------- problem constants ----------------
#define BB   128      // windows (= batch*nW)
#define LL   256      // tokens per window
#define NHEAD 4
#define HD   32
#define NT   225      // rpe table rows

// ---------------- scratch (static device globals) ----------------
__device__ float g_qkv[BB * LL * 384];      // [b][l][384]
__device__ float g_ctx[BB * LL * 128];      // [b][l][128]
__device__ float g_wqkvT[128 * 384];        // [k][n]
__device__ float g_wprojT[128 * 128];       // [k][n]

__device__ __forceinline__ void axpy(float a, const float4 b, float4& c) {
    c.x = fmaf(a, b.x, c.x); c.y = fmaf(a, b.y, c.y);
    c.z = fmaf(a, b.z, c.z); c.w = fmaf(a, b.w, c.w);
}
__device__ __forceinline__ float getc(float4 v, int kk) {
    return kk == 0 ? v.x : kk == 1 ? v.y : kk == 2 ? v.z : v.w;
}

// ---------------- dummy (ncu launch-index alignment) ------------
__global__ void k_dummy() {}

// ---------------- kernel 0: transpose weights ----------------
__global__ void k_transpose(const float* __restrict__ wq, const float* __restrict__ wp) {
    int e = blockIdx.x * 256 + threadIdx.x;
    if (e < 384 * 128) { int n = e >> 7, k = e & 127; g_wqkvT[k * 384 + n] = wq[e]; }
    if (e < 128 * 128) { int n = e >> 7, k = e & 127; g_wprojT[k * 128 + n] = wp[e]; }
}

// ---------------- GEMM: C[p,n] = A[p,:128] @ Bt[:128,n] + bias[n] ----------
#define GEMM_SMEM_BYTES (64 * 132 * 4 + 128 * 32 * 16)
__global__ void k_gemm(const float* __restrict__ A, const float* __restrict__ Bt,
                       const float* __restrict__ bias, float* __restrict__ C, int N) {
    extern __shared__ float sm[];
    float*  xs = sm;                          // [64][132]
    float4* ws = (float4*)(sm + 64 * 132);    // [128][32] float4

    int p0 = blockIdx.x * 64, n0 = blockIdx.y * 128;
    int tid = threadIdx.x;

    const float4* A4 = (const float4*)A;
#pragma unroll
    for (int it = 0; it < 8; ++it) {
        int e = it * 256 + tid; int r = e >> 5, k4 = e & 31;
        float4 v = A4[(p0 + r) * 32 + k4];
        *(float4*)&xs[r * 132 + k4 * 4] = v;
    }
    const float4* B4 = (const float4*)Bt; int N4 = N >> 2;
#pragma unroll
    for (int it = 0; it < 16; ++it) {
        int e = it * 256 + tid; int k = e >> 5, n4 = e & 31;
        ws[k * 32 + n4] = B4[k * N4 + (n0 >> 2) + n4];
    }
    __syncthreads();

    int tx = tid & 15, ty = tid >> 4;
    int i0 = ty * 4, eo = ty & 1;
    int jA = 2 * tx + eo, jB = 2 * tx + (1 ^ eo);

    float4 z = make_float4(0.f, 0.f, 0.f, 0.f);
    float4 aA0 = z, aA1 = z, aA2 = z, aA3 = z;
    float4 aB0 = z, aB1 = z, aB2 = z, aB3 = z;

#pragma unroll 8
    for (int k = 0; k < 128; ++k) {
        float4 bA = ws[k * 32 + jA];
        float4 bB = ws[k * 32 + jB];
        float a0 = xs[(i0 + 0) * 132 + k];
        float a1 = xs[(i0 + 1) * 132 + k];
        float a2 = xs[(i0 + 2) * 132 + k];
        float a3 = xs[(i0 + 3) * 132 + k];
        axpy(a0, bA, aA0); axpy(a1, bA, aA1); axpy(a2, bA, aA2); axpy(a3, bA, aA3);
        axpy(a0, bB, aB0); axpy(a1, bB, aB1); axpy(a2, bB, aB2); axpy(a3, bB, aB3);
    }

    int nA = n0 + jA * 4, nB = n0 + jB * 4;
    float4 bsA = *(const float4*)&bias[nA];
    float4 bsB = *(const float4*)&bias[nB];
    float4 accA[4] = {aA0, aA1, aA2, aA3};
    float4 accB[4] = {aB0, aB1, aB2, aB3};
#pragma unroll
    for (int r = 0; r < 4; ++r) {
        int row = p0 + i0 + r;
        float4 oa = accA[r]; oa.x += bsA.x; oa.y += bsA.y; oa.z += bsA.z; oa.w += bsA.w;
        float4 ob = accB[r]; ob.x += bsB.x; ob.y += bsB.y; ob.z += bsB.z; ob.w += bsB.w;
        *(float4*)&C[row * N + nA] = oa;
        *(float4*)&C[row * N + nB] = ob;
    }
}

// ---------------- fused window attention: one CTA per (b, h), 512 threads ---
// smem offsets in floats:
#define OFF_QT   0        // qT[32][260]  (scaled, c-major)
#define OFF_KT   8320     // kT[32][260]
#define OFF_V    16640    // v[256][32]
#define OFF_QR   24832    // q_rpe*scale [225][36] (float4 rows, pitch 9 f4)
#define OFF_KR   32932    // k_rpe       [225][36]
#define OFF_VR   41032    // v_rpe       [225][32]
#define OFF_SB   48232    // score/prob buffer [32][260]
#define OFF_SUMS 56552    // row sums [32]
#define OFF_REL  56584    // uint8 rel_idx [64*64] = 1024 floats
#define ATTN_SMEM_FLOATS (OFF_REL + 1024)
#define ATTN_SMEM_BYTES  (ATTN_SMEM_FLOATS * 4)   // 230,432 B

__global__ __launch_bounds__(512, 1)
void k_attn(const float* __restrict__ rpe_table,
            const float* __restrict__ mask,
            const int*   __restrict__ rel) {
    extern __shared__ float sm[];
    float* qT = sm + OFF_QT;
    float* kT = sm + OFF_KT;
    float* vS = sm + OFF_V;
    float* QR = sm + OFF_QR;
    float* KR = sm + OFF_KR;
    float* Sb = sm + OFF_SB;
    float* sums = sm + OFF_SUMS;
    unsigned char* srel = (unsigned char*)(sm + OFF_REL);

    int blk = blockIdx.x;
    int b = blk >> 2, h = blk & 3;
    int tid = threadIdx.x;
    const float scale = 0.17677669529663687f;  // 32^-0.5

    // rel_idx -> uint8 smem
    for (int e = tid; e < 4096; e += 512) srel[e] = (unsigned char)rel[e];

    // q (scaled, transposed), k (transposed), v (row-major)
    const float4* qkv4 = (const float4*)g_qkv;   // row pitch = 96 float4
#pragma unroll
    for (int it = 0; it < 4; ++it) {
        int e = it * 512 + tid;           // 2048 = 256 rows x 8 float4
        int i = e >> 3, c4 = e & 7;
        int base = (b * 256 + i) * 96;
        float4 qv = qkv4[base + h * 8 + c4];
        float4 kv = qkv4[base + 32 + h * 8 + c4];
        float4 vv = qkv4[base + 64 + h * 8 + c4];
        int c = c4 * 4;
        qT[(c + 0) * 260 + i] = qv.x * scale;
        qT[(c + 1) * 260 + i] = qv.y * scale;
        qT[(c + 2) * 260 + i] = qv.z * scale;
        qT[(c + 3) * 260 + i] = qv.w * scale;
        kT[(c + 0) * 260 + i] = kv.x;
        kT[(c + 1) * 260 + i] = kv.y;
        kT[(c + 2) * 260 + i] = kv.z;
        kT[(c + 3) * 260 + i] = kv.w;
        ((float4*)vS)[i * 8 + c4] = vv;
    }
    // per-head rpe slices (QR/KR pitch 36 for float4 loads)
    for (int e = tid; e < NT * 96; e += 512) {
        int t = e / 96, c = e - t * 96;
        float v = rpe_table[t * 384 + h * 96 + c];
        if (c < 32)      QR[t * 36 + c]        = v * scale;    // q_rpe (scaled)
        else if (c < 64) KR[t * 36 + (c - 32)] = v;            // k_rpe
        else             (sm + OFF_VR)[t * 32 + (c - 64)] = v; // v_rpe
    }
    __syncthreads();

    // phase thread mappings
    int tr = tid >> 6, tc = tid & 63;     // scores: 4 rows x 4 cols per thread
    int li = tr * 4;
    int jr = tid >> 4, jlane = tid & 15;  // softmax: 32 rows, 16 lanes per row
    int w    = tid >> 5;                  // PV warp
    int lane = tid & 31;
    int g    = w & 7;                     // 4-row group (0..7), one rel bin
    int jh   = w >> 3;                    // j-half (0/1)
    int q4   = lane >> 3;                 // j-subquarter within half
    int c4   = lane & 7;                  // out col group

    const float4* qf   = (const float4*)qT;
    const float4* kf   = (const float4*)kT;
    const float4* vf   = (const float4*)vS;
    const float4* vrf  = (const float4*)(sm + OFF_VR);
    const float4* QR4  = (const float4*)QR;
    const float4* KR4  = (const float4*)KR;
    const float4* mask4 = (const float4*)mask;
    float4* Sb4 = (float4*)Sb;
    float4* gc4 = (float4*)g_ctx;

    for (int ob = 0; ob < 8; ++ob) {
        // ---- scores: S = q·k + qr + kr + mask ----
        {
            int i0 = ob * 32 + li;            // global row (mult of 4)
            int I = i0 >> 2;                  // spatial row bin (== qT float4 col)
            int t = srel[I * 64 + tc];
            int t9 = t * 9;
            // prefetch mask (global) before the FMA wall
            int mbase = b * 16384 + i0 * 64 + tc;
            float4 mv0 = mask4[mbase];
            float4 mv1 = mask4[mbase + 64];
            float4 mv2 = mask4[mbase + 128];
            float4 mv3 = mask4[mbase + 192];

            float4 z = make_float4(0.f, 0.f, 0.f, 0.f);
            float4 acc0 = z, acc1 = z, acc2 = z, acc3 = z, kr4 = z;
            float qr0 = 0.f, qr1 = 0.f, qr2 = 0.f, qr3 = 0.f;
#pragma unroll
            for (int kc = 0; kc < 8; ++kc) {
                float4 kv4 = KR4[t9 + kc];
                float4 qv4 = QR4[t9 + kc];
#pragma unroll
                for (int kk = 0; kk < 4; ++kk) {
                    int k = kc * 4 + kk;
                    float4 a  = qf[k * 65 + I];
                    float4 bb = kf[k * 65 + tc];
                    float kv = getc(kv4, kk);
                    float qv = getc(qv4, kk);
                    axpy(a.x, bb, acc0); axpy(a.y, bb, acc1);
                    axpy(a.z, bb, acc2); axpy(a.w, bb, acc3);
                    qr0 = fmaf(a.x, kv, qr0); qr1 = fmaf(a.y, kv, qr1);
                    qr2 = fmaf(a.z, kv, qr2); qr3 = fmaf(a.w, kv, qr3);
                    axpy(qv, bb, kr4);
                }
            }
            float4 s;
            s.x = acc0.x + qr0 + kr4.x + mv0.x;
            s.y = acc0.y + qr0 + kr4.y + mv0.y;
            s.z = acc0.z + qr0 + kr4.z + mv0.z;
            s.w = acc0.w + qr0 + kr4.w + mv0.w;
            Sb4[(li + 0) * 65 + tc] = s;
            s.x = acc1.x + qr1 + kr4.x + mv1.x;
            s.y = acc1.y + qr1 + kr4.y + mv1.y;
            s.z = acc1.z + qr1 + kr4.z + mv1.z;
            s.w = acc1.w + qr1 + kr4.w + mv1.w;
            Sb4[(li + 1) * 65 + tc] = s;
            s.x = acc2.x + qr2 + kr4.x + mv2.x;
            s.y = acc2.y + qr2 + kr4.y + mv2.y;
            s.z = acc2.z + qr2 + kr4.z + mv2.z;
            s.w = acc2.w + qr2 + kr4.w + mv2.w;
            Sb4[(li + 2) * 65 + tc] = s;
            s.x = acc3.x + qr3 + kr4.x + mv3.x;
            s.y = acc3.y + qr3 + kr4.y + mv3.y;
            s.z = acc3.z + qr3 + kr4.z + mv3.z;
            s.w = acc3.w + qr3 + kr4.w + mv3.w;
            Sb4[(li + 3) * 65 + tc] = s;
        }
        __syncthreads();

        // ---- softmax (float4, 2-pass, UNNORMALIZED; sums -> smem) ----
        {
            float4* row4 = (float4*)(Sb + jr * 260);
            float4 v0 = row4[jlane];
            float4 v1 = row4[16 + jlane];
            float4 v2 = row4[32 + jlane];
            float4 v3 = row4[48 + jlane];
            float mx = fmaxf(fmaxf(fmaxf(v0.x, v0.y), fmaxf(v0.z, v0.w)),
                             fmaxf(fmaxf(v1.x, v1.y), fmaxf(v1.z, v1.w)));
            mx = fmaxf(mx, fmaxf(fmaxf(fmaxf(v2.x, v2.y), fmaxf(v2.z, v2.w)),
                                 fmaxf(fmaxf(v3.x, v3.y), fmaxf(v3.z, v3.w))));
#pragma unroll
            for (int o = 8; o > 0; o >>= 1) mx = fmaxf(mx, __shfl_xor_sync(0xffffffffu, mx, o));
            v0.x = __expf(v0.x - mx); v0.y = __expf(v0.y - mx);
            v0.z = __expf(v0.z - mx); v0.w = __expf(v0.w - mx);
            v1.x = __expf(v1.x - mx); v1.y = __expf(v1.y - mx);
            v1.z = __expf(v1.z - mx); v1.w = __expf(v1.w - mx);
            v2.x = __expf(v2.x - mx); v2.y = __expf(v2.y - mx);
            v2.z = __expf(v2.z - mx); v2.w = __expf(v2.w - mx);
            v3.x = __expf(v3.x - mx); v3.y = __expf(v3.y - mx);
            v3.z = __expf(v3.z - mx); v3.w = __expf(v3.w - mx);
            row4[jlane] = v0;
            row4[16 + jlane] = v1;
            row4[32 + jlane] = v2;
            row4[48 + jlane] = v3;
            float sum = ((v0.x + v0.y) + (v0.z + v0.w)) + ((v1.x + v1.y) + (v1.z + v1.w))
                      + ((v2.x + v2.y) + (v2.z + v2.w)) + ((v3.x + v3.y) + (v3.z + v3.w));
#pragma unroll
            for (int o = 8; o > 0; o >>= 1) sum += __shfl_xor_sync(0xffffffffu, sum, o);
            if (jlane == 0) sums[jr] = sum;
        }
        __syncthreads();

        // ---- PV + fused binned P*v_rpe (unnormalized; scale at epilogue) ----
        {
            const float4* s0 = Sb4 + (4 * g + 0) * 65;
            const float4* s1 = Sb4 + (4 * g + 1) * 65;
            const float4* s2 = Sb4 + (4 * g + 2) * 65;
            const float4* s3 = Sb4 + (4 * g + 3) * 65;
            int I = ob * 8 + g;
            const unsigned char* rrow = srel + I * 64;
            float4 a0 = make_float4(0.f, 0.f, 0.f, 0.f);
            float4 a1 = a0, a2 = a0, a3 = a0;
            int Jbase = jh * 32 + q4 * 8;
#pragma unroll
            for (int jj = 0; jj < 8; ++jj) {
                int J = Jbase + jj;
                float4 p0 = s0[J];
                float4 p1 = s1[J];
                float4 p2 = s2[J];
                float4 p3 = s3[J];
                float4 v0 = vf[(4 * J + 0) * 8 + c4];
                float4 v1 = vf[(4 * J + 1) * 8 + c4];
                float4 v2 = vf[(4 * J + 2) * 8 + c4];
                float4 v3 = vf[(4 * J + 3) * 8 + c4];
                axpy(p0.x, v0, a0); axpy(p0.y, v1, a0); axpy(p0.z, v2, a0); axpy(p0.w, v3, a0);
                axpy(p1.x, v0, a1); axpy(p1.y, v1, a1); axpy(p1.z, v2, a1); axpy(p1.w, v3, a1);
                axpy(p2.x, v0, a2); axpy(p2.y, v1, a2); axpy(p2.z, v2, a2); axpy(p2.w, v3, a2);
                axpy(p3.x, v0, a3); axpy(p3.y, v1, a3); axpy(p3.z, v2, a3); axpy(p3.w, v3, a3);
                float4 vr = vrf[rrow[J] * 8 + c4];
                axpy((p0.x + p0.y) + (p0.z + p0.w), vr, a0);
                axpy((p1.x + p1.y) + (p1.z + p1.w), vr, a1);
                axpy((p2.x + p2.y) + (p2.z + p2.w), vr, a2);
                axpy((p3.x + p3.y) + (p3.z + p3.w), vr, a3);
            }
            // reduce over q4 (lane bits 3,4)
#pragma unroll
            for (int o = 8; o <= 16; o <<= 1) {
                a0.x += __shfl_xor_sync(0xffffffffu, a0.x, o);
                a0.y += __shfl_xor_sync(0xffffffffu, a0.y, o);
                a0.z += __shfl_xor_sync(0xffffffffu, a0.z, o);
                a0.w += __shfl_xor_sync(0xffffffffu, a0.w, o);
                a1.x += __shfl_xor_sync(0xffffffffu, a1.x, o);
                a1.y += __shfl_xor_sync(0xffffffffu, a1.y, o);
                a1.z += __shfl_xor_sync(0xffffffffu, a1.z, o);
                a1.w += __shfl_xor_sync(0xffffffffu, a1.w, o);
                a2.x += __shfl_xor_sync(0xffffffffu, a2.x, o);
                a2.y += __shfl_xor_sync(0xffffffffu, a2.y, o);
                a2.z += __shfl_xor_sync(0xffffffffu, a2.z, o);
                a2.w += __shfl_xor_sync(0xffffffffu, a2.w, o);
                a3.x += __shfl_xor_sync(0xffffffffu, a3.x, o);
                a3.y += __shfl_xor_sync(0xffffffffu, a3.y, o);
                a3.z += __shfl_xor_sync(0xffffffffu, a3.z, o);
                a3.w += __shfl_xor_sync(0xffffffffu, a3.w, o);
            }
            // cross-half combine via Sb[0..255] scratch AFTER all P reads retire
            __syncthreads();
            if (jh == 1 && q4 == 0) {
                Sb4[(4 * g + 0) * 8 + c4] = a0;
                Sb4[(4 * g + 1) * 8 + c4] = a1;
                Sb4[(4 * g + 2) * 8 + c4] = a2;
                Sb4[(4 * g + 3) * 8 + c4] = a3;
            }
            __syncthreads();
            if (jh == 0 && q4 == 0) {
                int row0 = b * 256 + ob * 32 + 4 * g;
                float inv0 = 1.0f / sums[4 * g + 0];
                float inv1 = 1.0f / sums[4 * g + 1];
                float inv2 = 1.0f / sums[4 * g + 2];
                float inv3 = 1.0f / sums[4 * g + 3];
                float4 c0 = Sb4[(4 * g + 0) * 8 + c4];
                float4 c1 = Sb4[(4 * g + 1) * 8 + c4];
                float4 c2 = Sb4[(4 * g + 2) * 8 + c4];
                float4 c3 = Sb4[(4 * g + 3) * 8 + c4];
                a0.x = (a0.x + c0.x) * inv0; a0.y = (a0.y + c0.y) * inv0;
                a0.z = (a0.z + c0.z) * inv0; a0.w = (a0.w + c0.w) * inv0;
                a1.x = (a1.x + c1.x) * inv1; a1.y = (a1.y + c1.y) * inv1;
                a1.z = (a1.z + c1.z) * inv1; a1.w = (a1.w + c1.w) * inv1;
                a2.x = (a2.x + c2.x) * inv2; a2.y = (a2.y + c2.y) * inv2;
                a2.z = (a2.z + c2.z) * inv2; a2.w = (a2.w + c2.w) * inv2;
                a3.x = (a3.x + c3.x) * inv3; a3.y = (a3.y + c3.y) * inv3;
                a3.z = (a3.z + c3.z) * inv3; a3.w = (a3.w + c3.w) * inv3;
                gc4[(row0 + 0) * 32 + h * 8 + c4] = a0;
                gc4[(row0 + 1) * 32 + h * 8 + c4] = a1;
                gc4[(row0 + 2) * 32 + h * 8 + c4] = a2;
                gc4[(row0 + 3) * 32 + h * 8 + c4] = a3;
            }
        }
        __syncthreads();
    }
}

// ---------------- host ----------------
extern "C" void kernel_launch(void* const* d_in, const int* in_sizes, int n_in,
                              void* d_out, int out_size) {
    const float* x      = (const float*)d_in[0];
    const float* qkv_w  = (const float*)d_in[1];
    const float* qkv_b  = (const float*)d_in[2];
    const float* rpe    = (const float*)d_in[3];
    const float* proj_w = (const float*)d_in[4];
    const float* proj_b = (const float*)d_in[5];
    const float* mask   = (const float*)d_in[6];
    const int*   rel    = (const int*)d_in[7];
    float* out = (float*)d_out;

    float *p_qkv, *p_ctx, *p_wqkvT, *p_wprojT;
    cudaGetSymbolAddress((void**)&p_qkv,    g_qkv);
    cudaGetSymbolAddress((void**)&p_ctx,    g_ctx);
    cudaGetSymbolAddress((void**)&p_wqkvT,  g_wqkvT);
    cudaGetSymbolAddress((void**)&p_wprojT, g_wprojT);

    cudaFuncSetAttribute(k_gemm, cudaFuncAttributeMaxDynamicSharedMemorySize, GEMM_SMEM_BYTES);
    cudaFuncSetAttribute(k_attn, cudaFuncAttributeMaxDynamicSharedMemorySize, ATTN_SMEM_BYTES);

    // ncu alignment: k_attn at our launch index 3
    k_transpose<<<192, 256>>>(qkv_w, proj_w);                                   // 0
    k_gemm<<<dim3(BB * LL / 64, 3), 256, GEMM_SMEM_BYTES>>>(x, p_wqkvT, qkv_b, p_qkv, 384); // 1
    k_dummy<<<1, 32>>>();                                                        // 2
    k_attn<<<BB * NHEAD, 512, ATTN_SMEM_BYTES>>>(rpe, mask, rel);                // 3
    k_gemm<<<dim3(BB * LL / 64, 1), 256, GEMM_SMEM_BYTES>>>(p_ctx, p_wprojT, proj_b, out, 128); // 4
}